// round 13
// baseline (speedup 1.0000x reference)
#include <cuda_runtime.h>

// Problem constants (fixed by the dataset)
#define BB   256
#define NN   32
#define WW   1920
#define HH   1080
#define ROWS   (BB * NN)        // 8192
// Work units: [0, 2*ROWS) = x half-rows (240 float4), [2*ROWS, 3*ROWS) = y rows (270 float4)
#define NUNITS (3 * ROWS)       // 24576
#define WPB    8
#define GRIDX  (NUNITS / WPB)   // 3072 blocks
#define NSLOTS 32

// Scratch (__device__ globals; zero at load, reset by last block every launch
// so graph replays are deterministic).
__device__ float        g_accs[NSLOTS];
__device__ float        g_counts[NSLOTS];
__device__ unsigned int g_done;

__inline__ __device__ float warp_sum(float v) {
    #pragma unroll
    for (int o = 16; o > 0; o >>= 1)
        v += __shfl_xor_sync(0xffffffffu, v, o);
    return v;
}

// sum of clamp(log(1-p), -100) over a float4
__inline__ __device__ float l1term(float4 v) {
    return fmaxf(__logf(1.0f - v.x), -100.0f)
         + fmaxf(__logf(1.0f - v.y), -100.0f)
         + fmaxf(__logf(1.0f - v.z), -100.0f)
         + fmaxf(__logf(1.0f - v.w), -100.0f);
}

__global__ void __launch_bounds__(256)
hbdl_kernel(const float* __restrict__ px,
            const float* __restrict__ py,
            const long long* __restrict__ tgt,
            float* __restrict__ out) {
    const int tid  = threadIdx.x;
    const int lane = tid & 31;
    const int wid  = tid >> 5;
    const int uid  = blockIdx.x * WPB + wid;    // work unit id, [0, 24576)
    const bool is_x = (uid < 2 * ROWS);
    const int r    = is_x ? (uid >> 1) : (uid - 2 * ROWS);

    // --- mask + target for this unit's row (16B, L2-hot; lane 0 loads, broadcast) ---
    long long t0 = 0, t1 = 0;
    if (lane == 0) {
        longlong2 t2 = ((const longlong2*)tgt)[r];
        t0 = t2.x; t1 = t2.y;
    }
    int tx = __shfl_sync(0xffffffffu, (int)t0, 0);
    int ty = __shfl_sync(0xffffffffu, (int)t1, 0);
    tx = min(max(tx, 0), WW - 1);
    ty = min(max(ty, 0), HH - 1);
    const bool valid = !((tx == 0) && (ty == 0));   // warp-uniform

    float contrib = 0.0f;   // lane-0 value after warp reduce

    if (valid) {
        float s = 0.0f;
        if (is_x) {
            // x half-row: 240 float4 = 7 full warp-iters + 16-lane tail
            const int half = uid & 1;
            const float4* p4 = (const float4*)(px + (size_t)r * WW) + half * 240;
            #pragma unroll
            for (int k = 0; k < 7; k++)
                s += l1term(p4[k * 32 + lane]);
            if (lane < 16)
                s += l1term(p4[224 + lane]);

            float ws = warp_sum(s);
            if (lane == 0) {
                contrib = -ws * (1.0f / (float)WW);
                if (half == 0) {
                    // Both gather terms + count, once per row.
                    const float* rowx = px + (size_t)r * WW;
                    const float* rowy = py + (size_t)r * HH;
                    float p = rowx[tx];
                    float q = rowy[ty];
                    contrib += (fmaxf(__logf(1.0f - p), -100.0f)
                              - fmaxf(__logf(p),        -100.0f)) * (1.0f / (float)WW)
                             + (fmaxf(__logf(1.0f - q), -100.0f)
                              - fmaxf(__logf(q),        -100.0f)) * (1.0f / (float)HH);
                    atomicAdd(&g_counts[blockIdx.x & (NSLOTS - 1)], 1.0f);
                }
            }
        } else {
            // y row: 270 float4 = 8 full warp-iters + 14-lane tail
            const float4* p4 = (const float4*)(py + (size_t)r * HH);
            #pragma unroll
            for (int k = 0; k < 8; k++)
                s += l1term(p4[k * 32 + lane]);
            if (lane < 14)
                s += l1term(p4[256 + lane]);

            float ws = warp_sum(s);
            if (lane == 0)
                contrib = -ws * (1.0f / (float)HH);
        }
    }

    // --- block reduce (8 warps) -> one striped atomic per block ---
    __shared__ float sh[WPB];
    if (lane == 0) sh[wid] = contrib;
    __syncthreads();
    if (tid == 0) {
        float t = 0.0f;
        #pragma unroll
        for (int w = 0; w < WPB; w++) t += sh[w];
        atomicAdd(&g_accs[blockIdx.x & (NSLOTS - 1)], t);
    }

    // --- ticket: last block finalizes + resets scratch ---
    __shared__ bool isLast;
    if (tid == 0) {
        __threadfence();
        isLast = (atomicAdd(&g_done, 1u) == (unsigned)(GRIDX - 1));
    }
    __syncthreads();
    if (isLast && tid < NSLOTS) {
        volatile float* va = g_accs;
        volatile float* vc = g_counts;
        float a = va[tid];
        float c = vc[tid];
        a = warp_sum(a);
        c = warp_sum(c);
        if (tid == 0) {
            out[0] = a / fmaxf(c, 1.0f);
            g_done = 0u;
        }
        g_accs[tid]   = 0.0f;
        g_counts[tid] = 0.0f;
    }
}

extern "C" void kernel_launch(void* const* d_in, const int* in_sizes, int n_in,
                              void* d_out, int out_size) {
    const float*     px  = (const float*)d_in[0];       // [256,32,1920] f32
    const float*     py  = (const float*)d_in[1];       // [256,32,1080] f32
    const long long* tgt = (const long long*)d_in[2];   // [256,32,2] i64
    float* out = (float*)d_out;

    hbdl_kernel<<<GRIDX, 256>>>(px, py, tgt, out);
}

// round 14
// speedup vs baseline: 1.4110x; 1.4110x over previous
#include <cuda_runtime.h>

// Problem constants (fixed by the dataset)
#define BB   256
#define NN   32
#define WW   1920
#define HH   1080
#define ROWS   (BB * NN)        // 8192 rows; one warp per row (x-row + y-row)
#define WPB    8                // warps per block
#define GRIDX  (ROWS / WPB)     // 1024 blocks -> exactly one wave (~7 blocks/SM)
#define NSLOTS 32

// Scratch (__device__ globals; zero at load, reset by last block every launch
// so graph replays are deterministic).
__device__ float        g_accs[NSLOTS];
__device__ float        g_counts[NSLOTS];
__device__ unsigned int g_done;

__inline__ __device__ float warp_sum(float v) {
    #pragma unroll
    for (int o = 16; o > 0; o >>= 1)
        v += __shfl_xor_sync(0xffffffffu, v, o);
    return v;
}

// sum of clamp(log(1-p), -100) over a float4
__inline__ __device__ float l1term(float4 v) {
    return fmaxf(__logf(1.0f - v.x), -100.0f)
         + fmaxf(__logf(1.0f - v.y), -100.0f)
         + fmaxf(__logf(1.0f - v.z), -100.0f)
         + fmaxf(__logf(1.0f - v.w), -100.0f);
}

__global__ void __launch_bounds__(256)
hbdl_kernel(const float* __restrict__ px,
            const float* __restrict__ py,
            const long long* __restrict__ tgt,
            float* __restrict__ out) {
    const int tid  = threadIdx.x;
    const int lane = tid & 31;
    const int wid  = tid >> 5;
    const int r    = blockIdx.x * WPB + wid;    // row id, [0, 8192)

    // --- mask + target for this row (16B, L2-hot; lane 0 loads, broadcast) ---
    long long t0 = 0, t1 = 0;
    if (lane == 0) {
        longlong2 t2 = ((const longlong2*)tgt)[r];
        t0 = t2.x; t1 = t2.y;
    }
    int tx = __shfl_sync(0xffffffffu, (int)t0, 0);
    int ty = __shfl_sync(0xffffffffu, (int)t1, 0);
    tx = min(max(tx, 0), WW - 1);
    ty = min(max(ty, 0), HH - 1);
    const bool valid = !((tx == 0) && (ty == 0));   // warp-uniform

    float contrib = 0.0f;   // lane-0 value after warp reduce

    if (valid) {
        const float* rowx = px + (size_t)r * WW;
        const float* rowy = py + (size_t)r * HH;

        // x-row: 480 float4 = 15 full warp-iterations
        float sx = 0.0f;
        {
            const float4* p4 = (const float4*)rowx;
            #pragma unroll 5
            for (int k = 0; k < 15; k++)
                sx += l1term(p4[k * 32 + lane]);
        }

        // y-row: 270 float4 = 8 full warp-iterations + 14-lane tail
        float sy = 0.0f;
        {
            const float4* p4 = (const float4*)rowy;
            #pragma unroll
            for (int k = 0; k < 8; k++)
                sy += l1term(p4[k * 32 + lane]);
            if (lane < 14)
                sy += l1term(p4[256 + lane]);
        }

        // combine with per-axis 1/L weights before the warp reduce
        float ws = warp_sum(sx * (1.0f / (float)WW) + sy * (1.0f / (float)HH));

        if (lane == 0) {
            // row loss: (-lp[t] - (sum_l1p - l1p[t])) / L , per axis
            float p = rowx[tx];
            float q = rowy[ty];
            contrib = -ws
                    + (fmaxf(__logf(1.0f - p), -100.0f)
                     - fmaxf(__logf(p),        -100.0f)) * (1.0f / (float)WW)
                    + (fmaxf(__logf(1.0f - q), -100.0f)
                     - fmaxf(__logf(q),        -100.0f)) * (1.0f / (float)HH);
            atomicAdd(&g_counts[blockIdx.x & (NSLOTS - 1)], 1.0f);
        }
    }

    // --- block reduce (8 warps) -> one striped atomic per block ---
    __shared__ float sh[WPB];
    if (lane == 0) sh[wid] = contrib;
    __syncthreads();
    if (tid == 0) {
        float t = 0.0f;
        #pragma unroll
        for (int w = 0; w < WPB; w++) t += sh[w];
        atomicAdd(&g_accs[blockIdx.x & (NSLOTS - 1)], t);
    }

    // --- ticket: last block finalizes + resets scratch ---
    __shared__ bool isLast;
    if (tid == 0) {
        __threadfence();
        isLast = (atomicAdd(&g_done, 1u) == (unsigned)(GRIDX - 1));
    }
    __syncthreads();
    if (isLast && tid < NSLOTS) {
        volatile float* va = g_accs;
        volatile float* vc = g_counts;
        float a = va[tid];
        float c = vc[tid];
        a = warp_sum(a);
        c = warp_sum(c);
        if (tid == 0) {
            out[0] = a / fmaxf(c, 1.0f);
            g_done = 0u;
        }
        g_accs[tid]   = 0.0f;
        g_counts[tid] = 0.0f;
    }
}

extern "C" void kernel_launch(void* const* d_in, const int* in_sizes, int n_in,
                              void* d_out, int out_size) {
    const float*     px  = (const float*)d_in[0];       // [256,32,1920] f32
    const float*     py  = (const float*)d_in[1];       // [256,32,1080] f32
    const long long* tgt = (const long long*)d_in[2];   // [256,32,2] i64
    float* out = (float*)d_out;

    hbdl_kernel<<<GRIDX, 256>>>(px, py, tgt, out);
}